// round 1
// baseline (speedup 1.0000x reference)
#include <cuda_runtime.h>
#include <cuda_bf16.h>

#define D      256
#define MAXN2  8192
#define GRID_G 4
#define BR     64
#define BC     64

// Scratch (no allocations allowed): transposed normalized matrix + partials.
__device__ float g_znT[D * MAXN2];            // znT[k][row], 8 MB
__device__ float g_Spart[GRID_G * MAXN2];     // per-colgroup row exp-sums
__device__ float g_pos[GRID_G * MAXN2];       // per-colgroup positive-pair sim

// ---------------------------------------------------------------------------
// K1: normalize rows of [zi; zj] and write transposed (k-major) to g_znT.
// One warp per row: 32 lanes x 8 floats.
// ---------------------------------------------------------------------------
__global__ void __launch_bounds__(256) normalize_kernel(
    const float* __restrict__ zi, const float* __restrict__ zj, int N, int N2)
{
    int warp = threadIdx.x >> 5;
    int lane = threadIdx.x & 31;
    int row  = blockIdx.x * 8 + warp;
    if (row >= N2) return;
    const float* src = (row < N) ? (zi + (size_t)row * D)
                                 : (zj + (size_t)(row - N) * D);
    float4 v0 = ((const float4*)src)[lane];        // k = 4*lane   .. +3
    float4 v1 = ((const float4*)src)[lane + 32];   // k = 128+4*lane .. +3
    float ss = v0.x*v0.x + v0.y*v0.y + v0.z*v0.z + v0.w*v0.w
             + v1.x*v1.x + v1.y*v1.y + v1.z*v1.z + v1.w*v1.w;
    #pragma unroll
    for (int m = 16; m; m >>= 1) ss += __shfl_xor_sync(0xffffffffu, ss, m);
    float inv = 1.0f / fmaxf(sqrtf(ss), 1e-8f);
    int k0 = lane * 4;
    g_znT[(k0+0)*N2 + row] = v0.x * inv;
    g_znT[(k0+1)*N2 + row] = v0.y * inv;
    g_znT[(k0+2)*N2 + row] = v0.z * inv;
    g_znT[(k0+3)*N2 + row] = v0.w * inv;
    g_znT[(k0+128)*N2 + row] = v1.x * inv;
    g_znT[(k0+129)*N2 + row] = v1.y * inv;
    g_znT[(k0+130)*N2 + row] = v1.z * inv;
    g_znT[(k0+131)*N2 + row] = v1.w * inv;
}

// ---------------------------------------------------------------------------
// K2: 64-row block vs one column group (N2/GRID_G cols). 64x64 tiles,
// 4x4 register blocking, fused exp epilogue with static max = 2.0.
// Shared tiles stored k-major -> conflict-free LDS.128 reads & writes.
// ---------------------------------------------------------------------------
__global__ void __launch_bounds__(256) sim_kernel(int N, int N2)
{
    extern __shared__ float smem[];
    float* a_sh = smem;            // [D][BR]
    float* b_sh = smem + D * BR;   // [D][BC]
    __shared__ float rowS[BR];
    __shared__ float rowPos[BR];

    const int tid = threadIdx.x;
    const int tx  = tid & 15;       // 16 col-groups of 4
    const int ty  = tid >> 4;       // 16 row-groups of 4
    const int R0  = blockIdx.x * BR;
    const int g   = blockIdx.y;
    const int r4  = (tid & 15) * 4; // loader: float4 offset
    const int k0  = tid >> 4;       // loader: k within pass

    // Load A tile once (whole K dimension).
    #pragma unroll
    for (int kk = 0; kk < D; kk += 16) {
        int k = k0 + kk;
        *(float4*)&a_sh[k*BR + r4] = *(const float4*)&g_znT[k*N2 + R0 + r4];
    }
    if (tid < BR) { rowS[tid] = 0.0f; rowPos[tid] = 0.0f; }

    const int colsPerG = N2 / GRID_G;
    const int tiles    = colsPerG / BC;

    for (int ct = 0; ct < tiles; ct++) {
        const int C0 = g * colsPerG + ct * BC;
        __syncthreads();   // protect b_sh from prior tile's readers
        #pragma unroll
        for (int kk = 0; kk < D; kk += 16) {
            int k = k0 + kk;
            *(float4*)&b_sh[k*BC + r4] = *(const float4*)&g_znT[k*N2 + C0 + r4];
        }
        __syncthreads();

        float acc[4][4] = {};
        #pragma unroll 8
        for (int k = 0; k < D; k++) {
            float4 a = *(const float4*)&a_sh[k*BR + ty*4];
            float4 b = *(const float4*)&b_sh[k*BC + tx*4];
            acc[0][0] += a.x*b.x; acc[0][1] += a.x*b.y; acc[0][2] += a.x*b.z; acc[0][3] += a.x*b.w;
            acc[1][0] += a.y*b.x; acc[1][1] += a.y*b.y; acc[1][2] += a.y*b.z; acc[1][3] += a.y*b.w;
            acc[2][0] += a.z*b.x; acc[2][1] += a.z*b.y; acc[2][2] += a.z*b.z; acc[2][3] += a.z*b.w;
            acc[3][0] += a.w*b.x; acc[3][1] += a.w*b.y; acc[3][2] += a.w*b.z; acc[3][3] += a.w*b.w;
        }

        // Epilogue: sim = 2*dot; accumulate exp(sim-2) excluding diagonal,
        // capture positive-pair sim.
        #pragma unroll
        for (int i = 0; i < 4; i++) {
            int r     = R0 + ty*4 + i;
            int pairc = (r < N) ? (r + N) : (r - N);
            float s = 0.0f, pv = 0.0f;
            #pragma unroll
            for (int j = 0; j < 4; j++) {
                int   c   = C0 + tx*4 + j;
                float sim = 2.0f * acc[i][j];
                float e   = __expf(sim - 2.0f);
                if (c != r)    s += e;
                if (c == pairc) pv = sim;
            }
            #pragma unroll
            for (int m = 1; m < 16; m <<= 1) {
                s  += __shfl_xor_sync(0xffffffffu, s,  m);
                pv += __shfl_xor_sync(0xffffffffu, pv, m);
            }
            if (tx == 0) {
                rowS[ty*4 + i]   += s;    // row owned by exactly this lane
                rowPos[ty*4 + i] += pv;
            }
        }
    }
    __syncthreads();
    if (tid < BR) {
        g_Spart[g * MAXN2 + R0 + tid] = rowS[tid];
        g_pos  [g * MAXN2 + R0 + tid] = rowPos[tid];
    }
}

// ---------------------------------------------------------------------------
// K3: combine column-group partials, per-row loss, fp64 reduce, scalar out.
// ---------------------------------------------------------------------------
__global__ void __launch_bounds__(256) reduce_kernel(float* __restrict__ out, int N2)
{
    __shared__ double sh[256];
    double local = 0.0;
    for (int i = threadIdx.x; i < N2; i += 256) {
        float S = 0.0f, p = 0.0f;
        #pragma unroll
        for (int g = 0; g < GRID_G; g++) {
            S += g_Spart[g * MAXN2 + i];
            p += g_pos  [g * MAXN2 + i];
        }
        // lse_i = 2 + log(S); loss_i = lse_i - pos_i
        local += (double)(2.0f + logf(S) - p);
    }
    sh[threadIdx.x] = local;
    __syncthreads();
    #pragma unroll
    for (int s2 = 128; s2; s2 >>= 1) {
        if (threadIdx.x < s2) sh[threadIdx.x] += sh[threadIdx.x + s2];
        __syncthreads();
    }
    if (threadIdx.x == 0) out[0] = (float)(sh[0] / (double)N2);
}

// ---------------------------------------------------------------------------
extern "C" void kernel_launch(void* const* d_in, const int* in_sizes, int n_in,
                              void* d_out, int out_size)
{
    const float* zi = (const float*)d_in[0];
    const float* zj = (const float*)d_in[1];
    int N  = in_sizes[0] / D;   // 4096
    int N2 = 2 * N;             // 8192

    normalize_kernel<<<(N2 + 7) / 8, 256>>>(zi, zj, N, N2);

    size_t smem = (size_t)(D * BR + D * BC) * sizeof(float);  // 128 KB
    cudaFuncSetAttribute(sim_kernel,
                         cudaFuncAttributeMaxDynamicSharedMemorySize, (int)smem);
    sim_kernel<<<dim3(N2 / BR, GRID_G), 256, smem>>>(N, N2);

    reduce_kernel<<<1, 256>>>((float*)d_out, N2);
}

// round 3
// speedup vs baseline: 8.3884x; 8.3884x over previous
#include <cuda_runtime.h>
#include <cuda_bf16.h>
#include <cstdint>

#define D        256
#define N2MAX    8192
#define GROUPS   2
#define TILE     128
#define PAD      8
#define SSTRIDE  (D + PAD)            // 264 bf16 = 528 B (odd # of 16B units)
#define SBYTES   (TILE * SSTRIDE * 2) // 67584 B per tile

__device__ __align__(16) __nv_bfloat16 g_zn[N2MAX * D];
__device__ float g_S[GROUPS * N2MAX];
__device__ float g_pos[N2MAX / 2];

__device__ __forceinline__ uint32_t smem_u32(const void* p) {
    uint32_t a;
    asm("{ .reg .u64 t; cvta.to.shared.u64 t, %1; cvt.u32.u64 %0, t; }" : "=r"(a) : "l"(p));
    return a;
}
#define CP_ASYNC16(d, s) \
    asm volatile("cp.async.cg.shared.global [%0], [%1], 16;" :: "r"(d), "l"(s) : "memory")
#define CP_COMMIT()  asm volatile("cp.async.commit_group;" ::: "memory")
#define CP_WAIT0()   asm volatile("cp.async.wait_group 0;" ::: "memory")
#define LDSM4(r0, r1, r2, r3, a) \
    asm volatile("ldmatrix.sync.aligned.m8n8.x4.shared.b16 {%0,%1,%2,%3}, [%4];" \
                 : "=r"(r0), "=r"(r1), "=r"(r2), "=r"(r3) : "r"(a))
#define MMA(d, a, b) \
    asm volatile("mma.sync.aligned.m16n8k16.row.col.f32.bf16.bf16.f32 " \
                 "{%0,%1,%2,%3},{%4,%5,%6,%7},{%8,%9},{%0,%1,%2,%3};" \
                 : "+f"((d)[0]), "+f"((d)[1]), "+f"((d)[2]), "+f"((d)[3]) \
                 : "r"((a)[0]), "r"((a)[1]), "r"((a)[2]), "r"((a)[3]), \
                   "r"((b)[0]), "r"((b)[1]))

// async-copy one 128x256 bf16 tile (rows row0..row0+127) into padded smem
__device__ __forceinline__ void load_tile_async(uint32_t sbase, int row0, int tid) {
    #pragma unroll
    for (int i = 0; i < 16; i++) {
        int chunk = i * 256 + tid;        // 4096 x 16B
        int r   = chunk >> 5;
        int c16 = chunk & 31;
        const char* src = (const char*)(g_zn + (size_t)(row0 + r) * D) + c16 * 16;
        CP_ASYNC16(sbase + (uint32_t)(r * (SSTRIDE * 2) + c16 * 16), src);
    }
}

// ---------------------------------------------------------------------------
// K1: normalize pair (r, r+N) -> bf16 rows; exact fp32 positive-pair sim.
// ---------------------------------------------------------------------------
__global__ void __launch_bounds__(256) normalize_kernel(
    const float* __restrict__ zi, const float* __restrict__ zj, int N)
{
    int warp = threadIdx.x >> 5, lane = threadIdx.x & 31;
    int r = blockIdx.x * 8 + warp;
    if (r >= N) return;
    const float4* a = (const float4*)(zi + (size_t)r * D);
    const float4* b = (const float4*)(zj + (size_t)r * D);
    float4 a0 = a[lane], a1 = a[lane + 32];
    float4 b0 = b[lane], b1 = b[lane + 32];
    float sa = a0.x*a0.x+a0.y*a0.y+a0.z*a0.z+a0.w*a0.w + a1.x*a1.x+a1.y*a1.y+a1.z*a1.z+a1.w*a1.w;
    float sb = b0.x*b0.x+b0.y*b0.y+b0.z*b0.z+b0.w*b0.w + b1.x*b1.x+b1.y*b1.y+b1.z*b1.z+b1.w*b1.w;
    float dt = a0.x*b0.x+a0.y*b0.y+a0.z*b0.z+a0.w*b0.w + a1.x*b1.x+a1.y*b1.y+a1.z*b1.z+a1.w*b1.w;
    #pragma unroll
    for (int m = 16; m; m >>= 1) {
        sa += __shfl_xor_sync(0xffffffffu, sa, m);
        sb += __shfl_xor_sync(0xffffffffu, sb, m);
        dt += __shfl_xor_sync(0xffffffffu, dt, m);
    }
    float ia = 1.0f / fmaxf(sqrtf(sa), 1e-8f);
    float ib = 1.0f / fmaxf(sqrtf(sb), 1e-8f);
    if (lane == 0) g_pos[r] = 2.0f * dt * ia * ib;

    __nv_bfloat162* oa = (__nv_bfloat162*)(g_zn + (size_t)r * D);
    oa[2*lane]      = __nv_bfloat162(__float2bfloat16_rn(a0.x*ia), __float2bfloat16_rn(a0.y*ia));
    oa[2*lane + 1]  = __nv_bfloat162(__float2bfloat16_rn(a0.z*ia), __float2bfloat16_rn(a0.w*ia));
    oa[2*lane + 64] = __nv_bfloat162(__float2bfloat16_rn(a1.x*ia), __float2bfloat16_rn(a1.y*ia));
    oa[2*lane + 65] = __nv_bfloat162(__float2bfloat16_rn(a1.z*ia), __float2bfloat16_rn(a1.w*ia));
    __nv_bfloat162* ob = (__nv_bfloat162*)(g_zn + (size_t)(r + N) * D);
    ob[2*lane]      = __nv_bfloat162(__float2bfloat16_rn(b0.x*ib), __float2bfloat16_rn(b0.y*ib));
    ob[2*lane + 1]  = __nv_bfloat162(__float2bfloat16_rn(b0.z*ib), __float2bfloat16_rn(b0.w*ib));
    ob[2*lane + 64] = __nv_bfloat162(__float2bfloat16_rn(b1.x*ib), __float2bfloat16_rn(b1.y*ib));
    ob[2*lane + 65] = __nv_bfloat162(__float2bfloat16_rn(b1.z*ib), __float2bfloat16_rn(b1.w*ib));
}

// ---------------------------------------------------------------------------
// K2: HMMA (mma.sync bf16) GEMM + fused poly-exp2 row-sum epilogue.
// CTA = 128 rows x 4096 cols; A resident; B double-buffered via cp.async.
// ---------------------------------------------------------------------------
__global__ void __launch_bounds__(256) sim_kernel(int N2)
{
    extern __shared__ char sm[];
    __shared__ float rowS[4][TILE];

    const int tid  = threadIdx.x;
    const int wid  = tid >> 5;
    const int lane = tid & 31;
    const int wm   = wid & 1;     // 2 m-blocks of 64
    const int wn   = wid >> 1;    // 4 n-blocks of 32
    const int R0   = blockIdx.x * TILE;
    const int g    = blockIdx.y;
    const int colsPerG = N2 / GROUPS;
    const int tiles    = colsPerG / TILE;
    const int Cbase    = g * colsPerG;

    const uint32_t aB  = smem_u32(sm);
    const uint32_t bB0 = aB + SBYTES;
    const uint32_t bB1 = aB + 2 * SBYTES;

    load_tile_async(aB, R0, tid);
    load_tile_async(bB0, Cbase, tid);
    CP_COMMIT(); CP_WAIT0();
    __syncthreads();

    // per-warp ldmatrix base offsets
    const uint32_t aAddr = aB +
        (uint32_t)((wm * 64 + (lane & 15)) * (SSTRIDE * 2) + (lane >> 4) * 16);
    const uint32_t bOff =
        (uint32_t)((wn * 32 + (lane & 7) + ((lane >> 4) << 3)) * (SSTRIDE * 2) +
                   ((lane >> 3) & 1) * 16);

    float rs[8] = {0, 0, 0, 0, 0, 0, 0, 0};
    const float C1 = 0.69314718f, C2 = 0.24022651f, C3 = 0.05550411f, C4 = 0.00961813f;

    for (int ct = 0; ct < tiles; ct++) {
        const uint32_t bCur = (ct & 1) ? bB1 : bB0;
        const uint32_t bNext = (ct & 1) ? bB0 : bB1;
        if (ct + 1 < tiles) {
            load_tile_async(bNext, Cbase + (ct + 1) * TILE, tid);
            CP_COMMIT();
        }

        float acc[16][4];
        #pragma unroll
        for (int t = 0; t < 16; t++)
            #pragma unroll
            for (int j = 0; j < 4; j++) acc[t][j] = 0.0f;

        #pragma unroll
        for (int ks = 0; ks < 16; ks++) {
            uint32_t a[4][4], b[4][2];
            #pragma unroll
            for (int mt = 0; mt < 4; mt++)
                LDSM4(a[mt][0], a[mt][1], a[mt][2], a[mt][3],
                      aAddr + (uint32_t)(mt * 16 * (SSTRIDE * 2) + ks * 32));
            #pragma unroll
            for (int np = 0; np < 2; np++)
                LDSM4(b[np*2][0], b[np*2][1], b[np*2+1][0], b[np*2+1][1],
                      bCur + bOff + (uint32_t)(np * 16 * (SSTRIDE * 2) + ks * 32));
            #pragma unroll
            for (int mt = 0; mt < 4; mt++)
                #pragma unroll
                for (int nt = 0; nt < 4; nt++)
                    MMA(acc[mt * 4 + nt], a[mt], b[nt]);
        }

        // epilogue: sim = 2*acc; add exp(sim-2) via exp2 poly (no MUFU)
        #pragma unroll
        for (int t = 0; t < 16; t++)
            #pragma unroll
            for (int j = 0; j < 4; j++) {
                float y = fmaf(acc[t][j], 2.8853901f, -2.8853901f); // (2x-2)*log2e
                float z = __fadd_rn(y, 12582912.0f);
                float f = y - __fadd_rn(z, -12582912.0f);
                float p = fmaf(f, C4, C3);
                p = fmaf(f, p, C2);
                p = fmaf(f, p, C1);
                p = fmaf(f, p, 1.0f);
                rs[(t >> 2) * 2 + (j >> 1)] +=
                    __int_as_float(__float_as_int(p) + (__float_as_int(z) << 23));
            }

        if (ct + 1 < tiles) CP_WAIT0();
        __syncthreads();
    }

    // reduce: lanes l, l^1, l^2 share the same rows (differ only in columns)
    #pragma unroll
    for (int i = 0; i < 8; i++) {
        rs[i] += __shfl_xor_sync(0xffffffffu, rs[i], 1);
        rs[i] += __shfl_xor_sync(0xffffffffu, rs[i], 2);
    }
    if ((lane & 3) == 0) {
        #pragma unroll
        for (int mt = 0; mt < 4; mt++)
            #pragma unroll
            for (int h = 0; h < 2; h++)
                rowS[wn][wm * 64 + mt * 16 + h * 8 + (lane >> 2)] = rs[mt * 2 + h];
    }
    __syncthreads();
    if (tid < TILE)
        g_S[g * N2MAX + R0 + tid] =
            rowS[0][tid] + rowS[1][tid] + rowS[2][tid] + rowS[3][tid];
}

// ---------------------------------------------------------------------------
// K3: loss = [sum_i (2 + log(S_i - 1)) - 2*sum_r pos_r] / 2N
// ---------------------------------------------------------------------------
__global__ void __launch_bounds__(256) reduce_kernel(float* __restrict__ out, int N2)
{
    __shared__ double sh[256];
    double local = 0.0;
    for (int i = threadIdx.x; i < N2; i += 256) {
        float S = g_S[i] + g_S[N2MAX + i] - 1.0f;   // remove diagonal exp(0)=1
        local += (double)(2.0f + logf(S));
    }
    for (int r = threadIdx.x; r < N2 / 2; r += 256)
        local -= 2.0 * (double)g_pos[r];
    sh[threadIdx.x] = local;
    __syncthreads();
    #pragma unroll
    for (int s2 = 128; s2; s2 >>= 1) {
        if (threadIdx.x < s2) sh[threadIdx.x] += sh[threadIdx.x + s2];
        __syncthreads();
    }
    if (threadIdx.x == 0) out[0] = (float)(sh[0] / (double)N2);
}

// ---------------------------------------------------------------------------
extern "C" void kernel_launch(void* const* d_in, const int* in_sizes, int n_in,
                              void* d_out, int out_size)
{
    const float* zi = (const float*)d_in[0];
    const float* zj = (const float*)d_in[1];
    int N  = in_sizes[0] / D;     // 4096
    int N2 = 2 * N;               // 8192

    normalize_kernel<<<(N + 7) / 8, 256>>>(zi, zj, N);

    size_t smem = 3 * (size_t)SBYTES;   // 202752 B
    cudaFuncSetAttribute(sim_kernel,
                         cudaFuncAttributeMaxDynamicSharedMemorySize, (int)smem);
    sim_kernel<<<dim3(N2 / TILE, GROUPS), 256, smem>>>(N2);

    reduce_kernel<<<1, 256>>>((float*)d_out, N2);
}

// round 4
// speedup vs baseline: 13.1725x; 1.5703x over previous
#include <cuda_runtime.h>
#include <cuda_bf16.h>
#include <cstdint>

#define D        256
#define N2MAX    8192
#define TILE     128
#define NB       64                   // 8192 / 128 row-blocks
#define PAD      8
#define SSTRIDE  (D + PAD)            // 264 bf16 (odd # of 16B units)
#define SBYTES   (TILE * SSTRIDE * 2) // 67584 B per tile

__device__ __align__(16) __nv_bfloat16 g_zn[N2MAX * D];
__device__ float g_S[N2MAX];
__device__ float g_pos[N2MAX / 2];

__device__ __forceinline__ uint32_t smem_u32(const void* p) {
    uint32_t a;
    asm("{ .reg .u64 t; cvta.to.shared.u64 t, %1; cvt.u32.u64 %0, t; }" : "=r"(a) : "l"(p));
    return a;
}
#define CP_ASYNC16(d, s) \
    asm volatile("cp.async.cg.shared.global [%0], [%1], 16;" :: "r"(d), "l"(s) : "memory")
#define CP_COMMIT()  asm volatile("cp.async.commit_group;" ::: "memory")
#define CP_WAIT0()   asm volatile("cp.async.wait_group 0;" ::: "memory")
#define LDSM4(r0, r1, r2, r3, a) \
    asm volatile("ldmatrix.sync.aligned.m8n8.x4.shared.b16 {%0,%1,%2,%3}, [%4];" \
                 : "=r"(r0), "=r"(r1), "=r"(r2), "=r"(r3) : "r"(a))
#define MMA(d, a, b) \
    asm volatile("mma.sync.aligned.m16n8k16.row.col.f32.bf16.bf16.f32 " \
                 "{%0,%1,%2,%3},{%4,%5,%6,%7},{%8,%9},{%0,%1,%2,%3};" \
                 : "+f"((d)[0]), "+f"((d)[1]), "+f"((d)[2]), "+f"((d)[3]) \
                 : "r"((a)[0]), "r"((a)[1]), "r"((a)[2]), "r"((a)[3]), \
                   "r"((b)[0]), "r"((b)[1]))

__device__ __forceinline__ void load_tile_async(uint32_t sbase, int row0, int tid) {
    #pragma unroll
    for (int i = 0; i < 16; i++) {
        int chunk = i * 256 + tid;
        int r   = chunk >> 5;
        int c16 = chunk & 31;
        const char* src = (const char*)(g_zn + (size_t)(row0 + r) * D) + c16 * 16;
        CP_ASYNC16(sbase + (uint32_t)(r * (SSTRIDE * 2) + c16 * 16), src);
    }
}

// ---------------------------------------------------------------------------
// K1: normalize pair (r, r+N); also zero g_S.
// ---------------------------------------------------------------------------
__global__ void __launch_bounds__(256) normalize_kernel(
    const float* __restrict__ zi, const float* __restrict__ zj, int N)
{
    int gidx = blockIdx.x * 256 + threadIdx.x;
    if (gidx < N2MAX) g_S[gidx] = 0.0f;

    int warp = threadIdx.x >> 5, lane = threadIdx.x & 31;
    int r = blockIdx.x * 8 + warp;
    if (r >= N) return;
    const float4* a = (const float4*)(zi + (size_t)r * D);
    const float4* b = (const float4*)(zj + (size_t)r * D);
    float4 a0 = a[lane], a1 = a[lane + 32];
    float4 b0 = b[lane], b1 = b[lane + 32];
    float sa = a0.x*a0.x+a0.y*a0.y+a0.z*a0.z+a0.w*a0.w + a1.x*a1.x+a1.y*a1.y+a1.z*a1.z+a1.w*a1.w;
    float sb = b0.x*b0.x+b0.y*b0.y+b0.z*b0.z+b0.w*b0.w + b1.x*b1.x+b1.y*b1.y+b1.z*b1.z+b1.w*b1.w;
    float dt = a0.x*b0.x+a0.y*b0.y+a0.z*b0.z+a0.w*b0.w + a1.x*b1.x+a1.y*b1.y+a1.z*b1.z+a1.w*b1.w;
    #pragma unroll
    for (int m = 16; m; m >>= 1) {
        sa += __shfl_xor_sync(0xffffffffu, sa, m);
        sb += __shfl_xor_sync(0xffffffffu, sb, m);
        dt += __shfl_xor_sync(0xffffffffu, dt, m);
    }
    float ia = 1.0f / fmaxf(sqrtf(sa), 1e-8f);
    float ib = 1.0f / fmaxf(sqrtf(sb), 1e-8f);
    if (lane == 0) g_pos[r] = 2.0f * dt * ia * ib;

    __nv_bfloat162* oa = (__nv_bfloat162*)(g_zn + (size_t)r * D);
    oa[2*lane]      = __nv_bfloat162(__float2bfloat16_rn(a0.x*ia), __float2bfloat16_rn(a0.y*ia));
    oa[2*lane + 1]  = __nv_bfloat162(__float2bfloat16_rn(a0.z*ia), __float2bfloat16_rn(a0.w*ia));
    oa[2*lane + 64] = __nv_bfloat162(__float2bfloat16_rn(a1.x*ia), __float2bfloat16_rn(a1.y*ia));
    oa[2*lane + 65] = __nv_bfloat162(__float2bfloat16_rn(a1.z*ia), __float2bfloat16_rn(a1.w*ia));
    __nv_bfloat162* ob = (__nv_bfloat162*)(g_zn + (size_t)(r + N) * D);
    ob[2*lane]      = __nv_bfloat162(__float2bfloat16_rn(b0.x*ib), __float2bfloat16_rn(b0.y*ib));
    ob[2*lane + 1]  = __nv_bfloat162(__float2bfloat16_rn(b0.z*ib), __float2bfloat16_rn(b0.w*ib));
    ob[2*lane + 64] = __nv_bfloat162(__float2bfloat16_rn(b1.x*ib), __float2bfloat16_rn(b1.y*ib));
    ob[2*lane + 65] = __nv_bfloat162(__float2bfloat16_rn(b1.z*ib), __float2bfloat16_rn(b1.w*ib));
}

// ---------------------------------------------------------------------------
// K2: triangular HMMA GEMM. Pair (k, 63-k) = 65 tiles, split across 4 CTAs.
// Off-diag tile (i<j): row sums -> block i rows, col sums -> block j rows.
// ---------------------------------------------------------------------------
__global__ void __launch_bounds__(256) sim_kernel()
{
    extern __shared__ char sm[];
    const int tid  = threadIdx.x;
    const int wid  = tid >> 5;
    const int lane = tid & 31;
    const int wm   = wid & 1;
    const int wn   = wid >> 1;

    const int pairK = blockIdx.x >> 2;
    const int c4    = blockIdx.x & 3;
    const int n1    = NB - pairK;                 // tiles in row-block pairK
    const int lo    = (65 * c4) >> 2;
    const int hi    = (65 * (c4 + 1)) >> 2;

    const uint32_t aB  = smem_u32(sm);
    const uint32_t bB0 = aB + SBYTES;
    const uint32_t bB1 = aB + 2 * SBYTES;

    const uint32_t aAddr = aB +
        (uint32_t)((wm * 64 + (lane & 15)) * (SSTRIDE * 2) + (lane >> 4) * 16);
    const uint32_t bOff =
        (uint32_t)((wn * 32 + (lane & 7) + ((lane >> 4) << 3)) * (SSTRIDE * 2) +
                   ((lane >> 3) & 1) * 16);

    int i0, j0;
    { int t = lo; if (t < n1) { i0 = pairK; j0 = pairK + t; }
      else { i0 = NB - 1 - pairK; j0 = i0 + (t - n1); } }
    load_tile_async(aB, i0 * TILE, tid);
    load_tile_async(bB0, j0 * TILE, tid);
    CP_COMMIT(); CP_WAIT0();
    __syncthreads();

    float rs[8] = {0,0,0,0,0,0,0,0};
    const float C1 = 0.69314718f, C2 = 0.24022651f, C3 = 0.05550411f, C4c = 0.00961813f;
    int curI = i0;
    int pb = 0;

    for (int t = lo; t < hi; t++) {
        int i, j;
        if (t < n1) { i = pairK; j = pairK + t; }
        else        { i = NB - 1 - pairK; j = i + (t - n1); }
        int ni = -1, nj = -1;
        if (t + 1 < hi) {
            if (t + 1 < n1) { ni = pairK; nj = pairK + t + 1; }
            else            { ni = NB - 1 - pairK; nj = ni + (t + 1 - n1); }
        }
        const uint32_t bCur  = pb ? bB1 : bB0;
        const uint32_t bNext = pb ? bB0 : bB1;
        if (t + 1 < hi) { load_tile_async(bNext, nj * TILE, tid); CP_COMMIT(); }

        float acc[16][4];
        #pragma unroll
        for (int q = 0; q < 16; q++)
            #pragma unroll
            for (int v = 0; v < 4; v++) acc[q][v] = 0.0f;

        #pragma unroll
        for (int ks = 0; ks < 16; ks++) {
            uint32_t a[4][4], b[4][2];
            #pragma unroll
            for (int mt = 0; mt < 4; mt++)
                LDSM4(a[mt][0], a[mt][1], a[mt][2], a[mt][3],
                      aAddr + (uint32_t)(mt * 16 * (SSTRIDE * 2) + ks * 32));
            #pragma unroll
            for (int np = 0; np < 2; np++)
                LDSM4(b[np*2][0], b[np*2][1], b[np*2+1][0], b[np*2+1][1],
                      bCur + bOff + (uint32_t)(np * 16 * (SSTRIDE * 2) + ks * 32));
            #pragma unroll
            for (int mt = 0; mt < 4; mt++)
                #pragma unroll
                for (int nt = 0; nt < 4; nt++)
                    MMA(acc[mt * 4 + nt], a[mt], b[nt]);
        }

        // epilogue: e = exp(2*acc - 2) via exp2 poly
        const bool offdiag = (j != i);
        float cs[8] = {0,0,0,0,0,0,0,0};
        #pragma unroll
        for (int q = 0; q < 16; q++) {
            const int mt = q >> 2, nt = q & 3;
            #pragma unroll
            for (int v = 0; v < 4; v++) {
                float y = fmaf(acc[q][v], 2.8853901f, -2.8853901f);
                float z = __fadd_rn(y, 12582912.0f);
                float f = y - __fadd_rn(z, -12582912.0f);
                float p = fmaf(f, C4c, C3);
                p = fmaf(f, p, C2);
                p = fmaf(f, p, C1);
                p = fmaf(f, p, 1.0f);
                float e = __int_as_float(__float_as_int(p) + (__float_as_int(z) << 23));
                rs[mt * 2 + (v >> 1)] += e;
                cs[nt * 2 + (v & 1)]  += e;
            }
        }
        if (offdiag) {
            #pragma unroll
            for (int q = 0; q < 8; q++) {
                cs[q] += __shfl_xor_sync(0xffffffffu, cs[q], 4);
                cs[q] += __shfl_xor_sync(0xffffffffu, cs[q], 8);
                cs[q] += __shfl_xor_sync(0xffffffffu, cs[q], 16);
            }
            if (lane < 4) {
                const int C0 = j * TILE + wn * 32 + lane * 2;
                #pragma unroll
                for (int nt = 0; nt < 4; nt++) {
                    atomicAdd(&g_S[C0 + nt * 8],     cs[nt * 2]);
                    atomicAdd(&g_S[C0 + nt * 8 + 1], cs[nt * 2 + 1]);
                }
            }
        }

        if (t + 1 < hi) {
            if (ni != i) {
                __syncthreads();                 // all warps done reading A
                load_tile_async(aB, ni * TILE, tid);
                CP_COMMIT();
            }
            CP_WAIT0();
            __syncthreads();
        }
        // flush row sums when the row-block ends
        if (t + 1 >= hi || ni != i) {
            #pragma unroll
            for (int q = 0; q < 8; q++) {
                rs[q] += __shfl_xor_sync(0xffffffffu, rs[q], 1);
                rs[q] += __shfl_xor_sync(0xffffffffu, rs[q], 2);
            }
            if ((lane & 3) == 0) {
                const int R0 = i * TILE + wm * 64;
                #pragma unroll
                for (int mt = 0; mt < 4; mt++) {
                    atomicAdd(&g_S[R0 + mt * 16 +     (lane >> 2)], rs[mt * 2]);
                    atomicAdd(&g_S[R0 + mt * 16 + 8 + (lane >> 2)], rs[mt * 2 + 1]);
                }
            }
            #pragma unroll
            for (int q = 0; q < 8; q++) rs[q] = 0.0f;
        }
        pb ^= 1;
    }
}

// ---------------------------------------------------------------------------
// K3: loss = [sum_i (2 + log(S_i - 1)) - 2*sum_r pos_r] / 2N
// ---------------------------------------------------------------------------
__global__ void __launch_bounds__(256) reduce_kernel(float* __restrict__ out, int N2)
{
    __shared__ double sh[256];
    double local = 0.0;
    for (int i = threadIdx.x; i < N2; i += 256)
        local += (double)(2.0f + logf(g_S[i] - 1.0f));
    for (int r = threadIdx.x; r < N2 / 2; r += 256)
        local -= 2.0 * (double)g_pos[r];
    sh[threadIdx.x] = local;
    __syncthreads();
    #pragma unroll
    for (int s2 = 128; s2; s2 >>= 1) {
        if (threadIdx.x < s2) sh[threadIdx.x] += sh[threadIdx.x + s2];
        __syncthreads();
    }
    if (threadIdx.x == 0) out[0] = (float)(sh[0] / (double)N2);
}

// ---------------------------------------------------------------------------
extern "C" void kernel_launch(void* const* d_in, const int* in_sizes, int n_in,
                              void* d_out, int out_size)
{
    const float* zi = (const float*)d_in[0];
    const float* zj = (const float*)d_in[1];
    int N  = in_sizes[0] / D;     // 4096
    int N2 = 2 * N;               // 8192

    normalize_kernel<<<(N + 7) / 8, 256>>>(zi, zj, N);

    size_t smem = 3 * (size_t)SBYTES;   // 202752 B
    cudaFuncSetAttribute(sim_kernel,
                         cudaFuncAttributeMaxDynamicSharedMemorySize, (int)smem);
    sim_kernel<<<128, 256, smem>>>();

    reduce_kernel<<<1, 256>>>((float*)d_out, N2);
}

// round 5
// speedup vs baseline: 14.1000x; 1.0704x over previous
#include <cuda_runtime.h>
#include <cuda_bf16.h>
#include <cstdint>

#define D        256
#define N2MAX    8192
#define TILE     128
#define NB       64                   // 8192 / 128 row-blocks
#define NTILES   2080                 // NB*(NB+1)/2
#define NCTA     148
#define PAD      8
#define SSTRIDE  (D + PAD)            // 264 bf16 (odd # of 16B units)
#define SBYTES   (TILE * SSTRIDE * 2) // 67584 B per tile

__device__ __align__(16) __nv_bfloat16 g_zn[N2MAX * D];
__device__ float g_S[N2MAX];
__device__ float g_pos[N2MAX / 2];

__device__ __forceinline__ uint32_t smem_u32(const void* p) {
    uint32_t a;
    asm("{ .reg .u64 t; cvta.to.shared.u64 t, %1; cvt.u32.u64 %0, t; }" : "=r"(a) : "l"(p));
    return a;
}
#define CP_ASYNC16(d, s) \
    asm volatile("cp.async.cg.shared.global [%0], [%1], 16;" :: "r"(d), "l"(s) : "memory")
#define CP_COMMIT()  asm volatile("cp.async.commit_group;" ::: "memory")
#define CP_WAIT0()   asm volatile("cp.async.wait_group 0;" ::: "memory")
#define LDSM4(r0, r1, r2, r3, a) \
    asm volatile("ldmatrix.sync.aligned.m8n8.x4.shared.b16 {%0,%1,%2,%3}, [%4];" \
                 : "=r"(r0), "=r"(r1), "=r"(r2), "=r"(r3) : "r"(a))
#define MMA(d, a, b) \
    asm volatile("mma.sync.aligned.m16n8k16.row.col.f32.bf16.bf16.f32 " \
                 "{%0,%1,%2,%3},{%4,%5,%6,%7},{%8,%9},{%0,%1,%2,%3};" \
                 : "+f"((d)[0]), "+f"((d)[1]), "+f"((d)[2]), "+f"((d)[3]) \
                 : "r"((a)[0]), "r"((a)[1]), "r"((a)[2]), "r"((a)[3]), \
                   "r"((b)[0]), "r"((b)[1]))

__device__ __forceinline__ void load_tile_async(uint32_t sbase, int row0, int tid) {
    #pragma unroll
    for (int i = 0; i < 16; i++) {
        int chunk = i * 256 + tid;
        int r   = chunk >> 5;
        int c16 = chunk & 31;
        const char* src = (const char*)(g_zn + (size_t)(row0 + r) * D) + c16 * 16;
        CP_ASYNC16(sbase + (uint32_t)(r * (SSTRIDE * 2) + c16 * 16), src);
    }
}

// map global triangular tile index -> (i, j), i <= j
__device__ __forceinline__ void map_tile(int T, int& i, int& j) {
    int pair = T / 65;
    int s    = T - pair * 65;
    int n1   = NB - pair;
    if (s < n1) { i = pair;          j = pair + s; }
    else        { i = NB - 1 - pair; j = i + (s - n1); }
}

// ---------------------------------------------------------------------------
// K1: normalize pair (r, r+N); zero g_S. 1024 CTAs x 128 thr (occupancy).
// ---------------------------------------------------------------------------
__global__ void __launch_bounds__(128) normalize_kernel(
    const float* __restrict__ zi, const float* __restrict__ zj, int N)
{
    int gidx = blockIdx.x * 128 + threadIdx.x;
    if (gidx < N2MAX) g_S[gidx] = 0.0f;

    int warp = threadIdx.x >> 5, lane = threadIdx.x & 31;
    int r = blockIdx.x * 4 + warp;
    if (r >= N) return;
    const float4* a = (const float4*)(zi + (size_t)r * D);
    const float4* b = (const float4*)(zj + (size_t)r * D);
    float4 a0 = a[lane], a1 = a[lane + 32];
    float4 b0 = b[lane], b1 = b[lane + 32];
    float sa = a0.x*a0.x+a0.y*a0.y+a0.z*a0.z+a0.w*a0.w + a1.x*a1.x+a1.y*a1.y+a1.z*a1.z+a1.w*a1.w;
    float sb = b0.x*b0.x+b0.y*b0.y+b0.z*b0.z+b0.w*b0.w + b1.x*b1.x+b1.y*b1.y+b1.z*b1.z+b1.w*b1.w;
    float dt = a0.x*b0.x+a0.y*b0.y+a0.z*b0.z+a0.w*b0.w + a1.x*b1.x+a1.y*b1.y+a1.z*b1.z+a1.w*b1.w;
    #pragma unroll
    for (int m = 16; m; m >>= 1) {
        sa += __shfl_xor_sync(0xffffffffu, sa, m);
        sb += __shfl_xor_sync(0xffffffffu, sb, m);
        dt += __shfl_xor_sync(0xffffffffu, dt, m);
    }
    float ia = 1.0f / fmaxf(sqrtf(sa), 1e-8f);
    float ib = 1.0f / fmaxf(sqrtf(sb), 1e-8f);
    if (lane == 0) g_pos[r] = 2.0f * dt * ia * ib;

    __nv_bfloat162* oa = (__nv_bfloat162*)(g_zn + (size_t)r * D);
    oa[2*lane]      = __nv_bfloat162(__float2bfloat16_rn(a0.x*ia), __float2bfloat16_rn(a0.y*ia));
    oa[2*lane + 1]  = __nv_bfloat162(__float2bfloat16_rn(a0.z*ia), __float2bfloat16_rn(a0.w*ia));
    oa[2*lane + 64] = __nv_bfloat162(__float2bfloat16_rn(a1.x*ia), __float2bfloat16_rn(a1.y*ia));
    oa[2*lane + 65] = __nv_bfloat162(__float2bfloat16_rn(a1.z*ia), __float2bfloat16_rn(a1.w*ia));
    __nv_bfloat162* ob = (__nv_bfloat162*)(g_zn + (size_t)(r + N) * D);
    ob[2*lane]      = __nv_bfloat162(__float2bfloat16_rn(b0.x*ib), __float2bfloat16_rn(b0.y*ib));
    ob[2*lane + 1]  = __nv_bfloat162(__float2bfloat16_rn(b0.z*ib), __float2bfloat16_rn(b0.w*ib));
    ob[2*lane + 64] = __nv_bfloat162(__float2bfloat16_rn(b1.x*ib), __float2bfloat16_rn(b1.y*ib));
    ob[2*lane + 65] = __nv_bfloat162(__float2bfloat16_rn(b1.z*ib), __float2bfloat16_rn(b1.w*ib));
}

// ---------------------------------------------------------------------------
// K2: triangular HMMA GEMM, 148 CTAs, global tile-index partition (14-15/CTA).
// ---------------------------------------------------------------------------
__global__ void __launch_bounds__(256) sim_kernel()
{
    extern __shared__ char sm[];
    const int tid  = threadIdx.x;
    const int wid  = tid >> 5;
    const int lane = tid & 31;
    const int wm   = wid & 1;
    const int wn   = wid >> 1;

    const int lo = (NTILES * blockIdx.x) / NCTA;
    const int hi = (NTILES * (blockIdx.x + 1)) / NCTA;

    const uint32_t aB  = smem_u32(sm);
    const uint32_t bB0 = aB + SBYTES;
    const uint32_t bB1 = aB + 2 * SBYTES;

    const uint32_t aAddr = aB +
        (uint32_t)((wm * 64 + (lane & 15)) * (SSTRIDE * 2) + (lane >> 4) * 16);
    const uint32_t bOff =
        (uint32_t)((wn * 32 + (lane & 7) + ((lane >> 4) << 3)) * (SSTRIDE * 2) +
                   ((lane >> 3) & 1) * 16);

    int i0, j0;
    map_tile(lo, i0, j0);
    load_tile_async(aB, i0 * TILE, tid);
    load_tile_async(bB0, j0 * TILE, tid);
    CP_COMMIT(); CP_WAIT0();
    __syncthreads();

    float rs[8] = {0,0,0,0,0,0,0,0};
    const float C1 = 0.69314718f, C2 = 0.24022651f, C3 = 0.05550411f, C4c = 0.00961813f;
    int pb = 0;

    for (int t = lo; t < hi; t++) {
        int i, j;
        map_tile(t, i, j);
        int ni = -1, nj = -1;
        if (t + 1 < hi) map_tile(t + 1, ni, nj);

        const uint32_t bCur  = pb ? bB1 : bB0;
        const uint32_t bNext = pb ? bB0 : bB1;
        if (t + 1 < hi) { load_tile_async(bNext, nj * TILE, tid); CP_COMMIT(); }

        float acc[16][4];
        #pragma unroll
        for (int q = 0; q < 16; q++)
            #pragma unroll
            for (int v = 0; v < 4; v++) acc[q][v] = 0.0f;

        #pragma unroll
        for (int ks = 0; ks < 16; ks++) {
            uint32_t a[4][4], b[4][2];
            #pragma unroll
            for (int mt = 0; mt < 4; mt++)
                LDSM4(a[mt][0], a[mt][1], a[mt][2], a[mt][3],
                      aAddr + (uint32_t)(mt * 16 * (SSTRIDE * 2) + ks * 32));
            #pragma unroll
            for (int np = 0; np < 2; np++)
                LDSM4(b[np*2][0], b[np*2][1], b[np*2+1][0], b[np*2+1][1],
                      bCur + bOff + (uint32_t)(np * 16 * (SSTRIDE * 2) + ks * 32));
            #pragma unroll
            for (int mt = 0; mt < 4; mt++)
                #pragma unroll
                for (int nt = 0; nt < 4; nt++)
                    MMA(acc[mt * 4 + nt], a[mt], b[nt]);
        }

        // epilogue: e = exp(2*acc - 2) via exp2 poly (no MUFU)
        const bool offdiag = (j != i);
        float cs[8] = {0,0,0,0,0,0,0,0};
        #pragma unroll
        for (int q = 0; q < 16; q++) {
            const int mt = q >> 2, nt = q & 3;
            #pragma unroll
            for (int v = 0; v < 4; v++) {
                float y = fmaf(acc[q][v], 2.8853901f, -2.8853901f);
                float z = __fadd_rn(y, 12582912.0f);
                float f = y - __fadd_rn(z, -12582912.0f);
                float p = fmaf(f, C4c, C3);
                p = fmaf(f, p, C2);
                p = fmaf(f, p, C1);
                p = fmaf(f, p, 1.0f);
                float e = __int_as_float(__float_as_int(p) + (__float_as_int(z) << 23));
                rs[mt * 2 + (v >> 1)] += e;
                cs[nt * 2 + (v & 1)]  += e;
            }
        }
        if (offdiag) {
            #pragma unroll
            for (int q = 0; q < 8; q++) {
                cs[q] += __shfl_xor_sync(0xffffffffu, cs[q], 4);
                cs[q] += __shfl_xor_sync(0xffffffffu, cs[q], 8);
                cs[q] += __shfl_xor_sync(0xffffffffu, cs[q], 16);
            }
            if (lane < 4) {
                const int C0 = j * TILE + wn * 32 + lane * 2;
                #pragma unroll
                for (int nt = 0; nt < 4; nt++) {
                    atomicAdd(&g_S[C0 + nt * 8],     cs[nt * 2]);
                    atomicAdd(&g_S[C0 + nt * 8 + 1], cs[nt * 2 + 1]);
                }
            }
        }

        if (t + 1 < hi) {
            if (ni != i) {
                __syncthreads();
                load_tile_async(aB, ni * TILE, tid);
                CP_COMMIT();
            }
            CP_WAIT0();
            __syncthreads();
        }
        if (t + 1 >= hi || ni != i) {
            #pragma unroll
            for (int q = 0; q < 8; q++) {
                rs[q] += __shfl_xor_sync(0xffffffffu, rs[q], 1);
                rs[q] += __shfl_xor_sync(0xffffffffu, rs[q], 2);
            }
            if ((lane & 3) == 0) {
                const int R0 = i * TILE + wm * 64;
                #pragma unroll
                for (int mt = 0; mt < 4; mt++) {
                    atomicAdd(&g_S[R0 + mt * 16 +     (lane >> 2)], rs[mt * 2]);
                    atomicAdd(&g_S[R0 + mt * 16 + 8 + (lane >> 2)], rs[mt * 2 + 1]);
                }
            }
            #pragma unroll
            for (int q = 0; q < 8; q++) rs[q] = 0.0f;
        }
        pb ^= 1;
    }
}

// ---------------------------------------------------------------------------
// K3: loss = [sum_i (2 + log(S_i - 1)) - 2*sum_r pos_r] / 2N  (1024 thr, __logf)
// ---------------------------------------------------------------------------
__global__ void __launch_bounds__(1024) reduce_kernel(float* __restrict__ out, int N2)
{
    __shared__ double sh[1024];
    double local = 0.0;
    for (int i = threadIdx.x; i < N2; i += 1024)
        local += (double)(2.0f + __logf(g_S[i] - 1.0f));
    for (int r = threadIdx.x; r < N2 / 2; r += 1024)
        local -= 2.0 * (double)g_pos[r];
    sh[threadIdx.x] = local;
    __syncthreads();
    #pragma unroll
    for (int s2 = 512; s2; s2 >>= 1) {
        if (threadIdx.x < s2) sh[threadIdx.x] += sh[threadIdx.x + s2];
        __syncthreads();
    }
    if (threadIdx.x == 0) out[0] = (float)(sh[0] / (double)N2);
}

// ---------------------------------------------------------------------------
extern "C" void kernel_launch(void* const* d_in, const int* in_sizes, int n_in,
                              void* d_out, int out_size)
{
    const float* zi = (const float*)d_in[0];
    const float* zj = (const float*)d_in[1];
    int N  = in_sizes[0] / D;     // 4096
    int N2 = 2 * N;               // 8192

    normalize_kernel<<<(N + 3) / 4, 128>>>(zi, zj, N);

    size_t smem = 3 * (size_t)SBYTES;   // 202752 B
    cudaFuncSetAttribute(sim_kernel,
                         cudaFuncAttributeMaxDynamicSharedMemorySize, (int)smem);
    sim_kernel<<<NCTA, 256, smem>>>();

    reduce_kernel<<<1, 1024>>>((float*)d_out, N2);
}

// round 6
// speedup vs baseline: 14.2225x; 1.0087x over previous
#include <cuda_runtime.h>
#include <cuda_bf16.h>
#include <cstdint>

#define D        256
#define N2MAX    8192
#define TILE     128
#define NB       64
#define NTILES   2080                 // NB*(NB+1)/2
#define NCTA     148
#define PAD      8
#define SSTRIDE  (D + PAD)            // 264 bf16 (odd # of 16B units)
#define SBYTES   (TILE * SSTRIDE * 2) // 67584 B per tile

__device__ __align__(16) __nv_bfloat16 g_zn[N2MAX * D];
__device__ float g_S[N2MAX];
__device__ float g_pos[N2MAX / 2];

__device__ __forceinline__ uint32_t smem_u32(const void* p) {
    uint32_t a;
    asm("{ .reg .u64 t; cvta.to.shared.u64 t, %1; cvt.u32.u64 %0, t; }" : "=r"(a) : "l"(p));
    return a;
}
#define CP_ASYNC16(d, s) \
    asm volatile("cp.async.cg.shared.global [%0], [%1], 16;" :: "r"(d), "l"(s) : "memory")
#define CP_COMMIT()  asm volatile("cp.async.commit_group;" ::: "memory")
#define CP_WAIT0()   asm volatile("cp.async.wait_group 0;" ::: "memory")
#define LDSM4(r0, r1, r2, r3, a) \
    asm volatile("ldmatrix.sync.aligned.m8n8.x4.shared.b16 {%0,%1,%2,%3}, [%4];" \
                 : "=r"(r0), "=r"(r1), "=r"(r2), "=r"(r3) : "r"(a))
#define MMA(d, a, b) \
    asm volatile("mma.sync.aligned.m16n8k16.row.col.f32.bf16.bf16.f32 " \
                 "{%0,%1,%2,%3},{%4,%5,%6,%7},{%8,%9},{%0,%1,%2,%3};" \
                 : "+f"((d)[0]), "+f"((d)[1]), "+f"((d)[2]), "+f"((d)[3]) \
                 : "r"((a)[0]), "r"((a)[1]), "r"((a)[2]), "r"((a)[3]), \
                   "r"((b)[0]), "r"((b)[1]))

#define EC1 0.69314718f
#define EC2 0.24022651f
#define EC3 0.05550411f
#define EC4 0.00961813f
// e = exp(2*x - 2) via exp2 polynomial (no MUFU)
#define EXPSTEP(x, e) { \
    float y = fmaf((x), 2.8853901f, -2.8853901f); \
    float z = __fadd_rn(y, 12582912.0f); \
    float f = y - __fadd_rn(z, -12582912.0f); \
    float p = fmaf(f, EC4, EC3); \
    p = fmaf(f, p, EC2); \
    p = fmaf(f, p, EC1); \
    p = fmaf(f, p, 1.0f); \
    (e) = __int_as_float(__float_as_int(p) + (__float_as_int(z) << 23)); }

__device__ __forceinline__ void load_tile_async(uint32_t sbase, int row0, int tid) {
    #pragma unroll
    for (int i = 0; i < 16; i++) {
        int chunk = i * 256 + tid;
        int r   = chunk >> 5;
        int c16 = chunk & 31;
        const char* src = (const char*)(g_zn + (size_t)(row0 + r) * D) + c16 * 16;
        CP_ASYNC16(sbase + (uint32_t)(r * (SSTRIDE * 2) + c16 * 16), src);
    }
}

__device__ __forceinline__ void map_tile(int T, int& i, int& j) {
    int pair = T / 65;
    int s    = T - pair * 65;
    int n1   = NB - pair;
    if (s < n1) { i = pair;          j = pair + s; }
    else        { i = NB - 1 - pair; j = i + (s - n1); }
}

// GEMM k-loop for one 128x128 tile; if EPI, interleave the exp epilogue of the
// previous tile (prev) into the 16 k-steps (4 elements per step).
template<bool EPI>
__device__ __forceinline__ void mma_tile(
    uint32_t aAddr, uint32_t bAddr,
    float (&acc)[16][4], float (&prev)[16][4],
    float (&rs)[8], float (&cs)[8])
{
    #pragma unroll
    for (int q = 0; q < 16; q++)
        #pragma unroll
        for (int v = 0; v < 4; v++) acc[q][v] = 0.0f;
    #pragma unroll
    for (int ks = 0; ks < 16; ks++) {
        uint32_t a[4][4], b[4][2];
        #pragma unroll
        for (int mt = 0; mt < 4; mt++)
            LDSM4(a[mt][0], a[mt][1], a[mt][2], a[mt][3],
                  aAddr + (uint32_t)(mt * 16 * (SSTRIDE * 2) + ks * 32));
        #pragma unroll
        for (int np = 0; np < 2; np++)
            LDSM4(b[np*2][0], b[np*2][1], b[np*2+1][0], b[np*2+1][1],
                  bAddr + (uint32_t)(np * 16 * (SSTRIDE * 2) + ks * 32));
        #pragma unroll
        for (int mt = 0; mt < 4; mt++)
            #pragma unroll
            for (int nt = 0; nt < 4; nt++)
                MMA(acc[mt * 4 + nt], a[mt], b[nt]);
        if (EPI) {
            const int q = ks, mt = ks >> 2, nt = ks & 3;
            #pragma unroll
            for (int v = 0; v < 4; v++) {
                float e;
                EXPSTEP(prev[q][v], e);
                rs[mt * 2 + (v >> 1)] += e;
                cs[nt * 2 + (v & 1)]  += e;
            }
        }
    }
}

// ---------------------------------------------------------------------------
// K1: normalize pair (r, r+N); zero g_S.
// ---------------------------------------------------------------------------
__global__ void __launch_bounds__(128) normalize_kernel(
    const float* __restrict__ zi, const float* __restrict__ zj, int N)
{
    int gidx = blockIdx.x * 128 + threadIdx.x;
    if (gidx < N2MAX) g_S[gidx] = 0.0f;

    int warp = threadIdx.x >> 5, lane = threadIdx.x & 31;
    int r = blockIdx.x * 4 + warp;
    if (r >= N) return;
    const float4* a = (const float4*)(zi + (size_t)r * D);
    const float4* b = (const float4*)(zj + (size_t)r * D);
    float4 a0 = a[lane], a1 = a[lane + 32];
    float4 b0 = b[lane], b1 = b[lane + 32];
    float sa = a0.x*a0.x+a0.y*a0.y+a0.z*a0.z+a0.w*a0.w + a1.x*a1.x+a1.y*a1.y+a1.z*a1.z+a1.w*a1.w;
    float sb = b0.x*b0.x+b0.y*b0.y+b0.z*b0.z+b0.w*b0.w + b1.x*b1.x+b1.y*b1.y+b1.z*b1.z+b1.w*b1.w;
    float dt = a0.x*b0.x+a0.y*b0.y+a0.z*b0.z+a0.w*b0.w + a1.x*b1.x+a1.y*b1.y+a1.z*b1.z+a1.w*b1.w;
    #pragma unroll
    for (int m = 16; m; m >>= 1) {
        sa += __shfl_xor_sync(0xffffffffu, sa, m);
        sb += __shfl_xor_sync(0xffffffffu, sb, m);
        dt += __shfl_xor_sync(0xffffffffu, dt, m);
    }
    float ia = 1.0f / fmaxf(sqrtf(sa), 1e-8f);
    float ib = 1.0f / fmaxf(sqrtf(sb), 1e-8f);
    if (lane == 0) g_pos[r] = 2.0f * dt * ia * ib;

    __nv_bfloat162* oa = (__nv_bfloat162*)(g_zn + (size_t)r * D);
    oa[2*lane]      = __nv_bfloat162(__float2bfloat16_rn(a0.x*ia), __float2bfloat16_rn(a0.y*ia));
    oa[2*lane + 1]  = __nv_bfloat162(__float2bfloat16_rn(a0.z*ia), __float2bfloat16_rn(a0.w*ia));
    oa[2*lane + 64] = __nv_bfloat162(__float2bfloat16_rn(a1.x*ia), __float2bfloat16_rn(a1.y*ia));
    oa[2*lane + 65] = __nv_bfloat162(__float2bfloat16_rn(a1.z*ia), __float2bfloat16_rn(a1.w*ia));
    __nv_bfloat162* ob = (__nv_bfloat162*)(g_zn + (size_t)(r + N) * D);
    ob[2*lane]      = __nv_bfloat162(__float2bfloat16_rn(b0.x*ib), __float2bfloat16_rn(b0.y*ib));
    ob[2*lane + 1]  = __nv_bfloat162(__float2bfloat16_rn(b0.z*ib), __float2bfloat16_rn(b0.w*ib));
    ob[2*lane + 64] = __nv_bfloat162(__float2bfloat16_rn(b1.x*ib), __float2bfloat16_rn(b1.y*ib));
    ob[2*lane + 65] = __nv_bfloat162(__float2bfloat16_rn(b1.z*ib), __float2bfloat16_rn(b1.w*ib));
}

// ---------------------------------------------------------------------------
// K2: triangular HMMA GEMM, 148 CTAs; epilogue of tile t-1 pipelined under
// the MMA k-loop of tile t.
// ---------------------------------------------------------------------------
__global__ void __launch_bounds__(256, 1) sim_kernel()
{
    extern __shared__ char sm[];
    const int tid  = threadIdx.x;
    const int wid  = tid >> 5;
    const int lane = tid & 31;
    const int wm   = wid & 1;
    const int wn   = wid >> 1;

    const int lo = (NTILES * blockIdx.x) / NCTA;
    const int hi = (NTILES * (blockIdx.x + 1)) / NCTA;

    const uint32_t aB  = smem_u32(sm);
    const uint32_t bB0 = aB + SBYTES;
    const uint32_t bB1 = aB + 2 * SBYTES;

    const uint32_t aAddr = aB +
        (uint32_t)((wm * 64 + (lane & 15)) * (SSTRIDE * 2) + (lane >> 4) * 16);
    const uint32_t bOff =
        (uint32_t)((wn * 32 + (lane & 7) + ((lane >> 4) << 3)) * (SSTRIDE * 2) +
                   ((lane >> 3) & 1) * 16);

    float acc[16][4], prev[16][4];
    float rs[8] = {0,0,0,0,0,0,0,0};
    float cs[8];

    int i, j;
    map_tile(lo, i, j);
    load_tile_async(aB, i * TILE, tid);
    load_tile_async(bB0, j * TILE, tid);
    CP_COMMIT(); CP_WAIT0();
    __syncthreads();

    // --- peeled first tile (no previous epilogue) ---
    int ni = -1, nj = -1;
    if (lo + 1 < hi) {
        map_tile(lo + 1, ni, nj);
        load_tile_async(bB1, nj * TILE, tid);
        CP_COMMIT();
    }
    mma_tile<false>(aAddr, bB0 + bOff, acc, prev, rs, cs);
    #pragma unroll
    for (int q = 0; q < 16; q++)
        #pragma unroll
        for (int v = 0; v < 4; v++) prev[q][v] = acc[q][v];
    int iP = i, jP = j;
    if (lo + 1 < hi) {
        if (ni != i) { __syncthreads(); load_tile_async(aB, ni * TILE, tid); CP_COMMIT(); }
        CP_WAIT0(); __syncthreads();
    }

    int pb = 1;
    for (int t = lo + 1; t < hi; t++) {
        i = ni; j = nj;
        if (t + 1 < hi) {
            map_tile(t + 1, ni, nj);
            load_tile_async(pb ? bB0 : bB1, nj * TILE, tid);
            CP_COMMIT();
        } else ni = -1;

        #pragma unroll
        for (int q = 0; q < 8; q++) cs[q] = 0.0f;
        mma_tile<true>(aAddr, (pb ? bB1 : bB0) + bOff, acc, prev, rs, cs);

        // finish tile t-1: column sums -> rows of jP; flush rs if row-block ends
        if (jP != iP) {
            #pragma unroll
            for (int q = 0; q < 8; q++) {
                cs[q] += __shfl_xor_sync(0xffffffffu, cs[q], 4);
                cs[q] += __shfl_xor_sync(0xffffffffu, cs[q], 8);
                cs[q] += __shfl_xor_sync(0xffffffffu, cs[q], 16);
            }
            if (lane < 4) {
                const int C0 = jP * TILE + wn * 32 + lane * 2;
                #pragma unroll
                for (int nt = 0; nt < 4; nt++) {
                    atomicAdd(&g_S[C0 + nt * 8],     cs[nt * 2]);
                    atomicAdd(&g_S[C0 + nt * 8 + 1], cs[nt * 2 + 1]);
                }
            }
        }
        if (iP != i) {
            #pragma unroll
            for (int q = 0; q < 8; q++) {
                rs[q] += __shfl_xor_sync(0xffffffffu, rs[q], 1);
                rs[q] += __shfl_xor_sync(0xffffffffu, rs[q], 2);
            }
            if ((lane & 3) == 0) {
                const int R0 = iP * TILE + wm * 64;
                #pragma unroll
                for (int mt = 0; mt < 4; mt++) {
                    atomicAdd(&g_S[R0 + mt * 16 +     (lane >> 2)], rs[mt * 2]);
                    atomicAdd(&g_S[R0 + mt * 16 + 8 + (lane >> 2)], rs[mt * 2 + 1]);
                }
            }
            #pragma unroll
            for (int q = 0; q < 8; q++) rs[q] = 0.0f;
        }

        #pragma unroll
        for (int q = 0; q < 16; q++)
            #pragma unroll
            for (int v = 0; v < 4; v++) prev[q][v] = acc[q][v];
        iP = i; jP = j;

        if (t + 1 < hi) {
            if (ni != i) { __syncthreads(); load_tile_async(aB, ni * TILE, tid); CP_COMMIT(); }
            CP_WAIT0(); __syncthreads();
        }
        pb ^= 1;
    }

    // --- drain: epilogue of the last tile ---
    #pragma unroll
    for (int q = 0; q < 8; q++) cs[q] = 0.0f;
    #pragma unroll
    for (int q = 0; q < 16; q++) {
        const int mt = q >> 2, nt = q & 3;
        #pragma unroll
        for (int v = 0; v < 4; v++) {
            float e;
            EXPSTEP(prev[q][v], e);
            rs[mt * 2 + (v >> 1)] += e;
            cs[nt * 2 + (v & 1)]  += e;
        }
    }
    if (jP != iP) {
        #pragma unroll
        for (int q = 0; q < 8; q++) {
            cs[q] += __shfl_xor_sync(0xffffffffu, cs[q], 4);
            cs[q] += __shfl_xor_sync(0xffffffffu, cs[q], 8);
            cs[q] += __shfl_xor_sync(0xffffffffu, cs[q], 16);
        }
        if (lane < 4) {
            const int C0 = jP * TILE + wn * 32 + lane * 2;
            #pragma unroll
            for (int nt = 0; nt < 4; nt++) {
                atomicAdd(&g_S[C0 + nt * 8],     cs[nt * 2]);
                atomicAdd(&g_S[C0 + nt * 8 + 1], cs[nt * 2 + 1]);
            }
        }
    }
    #pragma unroll
    for (int q = 0; q < 8; q++) {
        rs[q] += __shfl_xor_sync(0xffffffffu, rs[q], 1);
        rs[q] += __shfl_xor_sync(0xffffffffu, rs[q], 2);
    }
    if ((lane & 3) == 0) {
        const int R0 = iP * TILE + wm * 64;
        #pragma unroll
        for (int mt = 0; mt < 4; mt++) {
            atomicAdd(&g_S[R0 + mt * 16 +     (lane >> 2)], rs[mt * 2]);
            atomicAdd(&g_S[R0 + mt * 16 + 8 + (lane >> 2)], rs[mt * 2 + 1]);
        }
    }
}

// ---------------------------------------------------------------------------
// K3: loss = [sum_i (2 + log(S_i - 1)) - 2*sum_r pos_r] / 2N
// ---------------------------------------------------------------------------
__global__ void __launch_bounds__(1024) reduce_kernel(float* __restrict__ out, int N2)
{
    __shared__ double sh[1024];
    double local = 0.0;
    for (int i = threadIdx.x; i < N2; i += 1024)
        local += (double)(2.0f + __logf(g_S[i] - 1.0f));
    for (int r = threadIdx.x; r < N2 / 2; r += 1024)
        local -= 2.0 * (double)g_pos[r];
    sh[threadIdx.x] = local;
    __syncthreads();
    #pragma unroll
    for (int s2 = 512; s2; s2 >>= 1) {
        if (threadIdx.x < s2) sh[threadIdx.x] += sh[threadIdx.x + s2];
        __syncthreads();
    }
    if (threadIdx.x == 0) out[0] = (float)(sh[0] / (double)N2);
}

// ---------------------------------------------------------------------------
extern "C" void kernel_launch(void* const* d_in, const int* in_sizes, int n_in,
                              void* d_out, int out_size)
{
    const float* zi = (const float*)d_in[0];
    const float* zj = (const float*)d_in[1];
    int N  = in_sizes[0] / D;     // 4096
    int N2 = 2 * N;               // 8192

    normalize_kernel<<<(N + 3) / 4, 128>>>(zi, zj, N);

    size_t smem = 3 * (size_t)SBYTES;   // 202752 B
    cudaFuncSetAttribute(sim_kernel,
                         cudaFuncAttributeMaxDynamicSharedMemorySize, (int)smem);
    sim_kernel<<<NCTA, 256, smem>>>();

    reduce_kernel<<<1, 1024>>>((float*)d_out, N2);
}